// round 10
// baseline (speedup 1.0000x reference)
#include <cuda_runtime.h>
#include <cuda_bf16.h>

// Problem constants
#define BB 4
#define NN 8192
#define PP 2048
#define CC 64
#define SS 32
#define NCH 68          // 3 xyz + 1 density + 64 features
#define WARPS_PER_BLK 4
#define TPAD 37         // 36-channel half-tile + 1 pad (odd -> conflict-free)

// Scratch (device globals: allocation is forbidden)
__device__ float4 g_xyz4[BB * NN];                       // 512 KB, padded xyz
__device__ float  g_featT[(size_t)BB * NN * CC];         // 8 MB, features (B, N, C)
__device__ int    g_idx[(size_t)BB * PP * SS];           // 1 MB, padded neighbor ids

// ---------------------------------------------------------------------------
// Fused prep: (a) xyz (B,N,3) -> float4   (b) transpose features (B,C,N)->(B,N,C)
// grid: (N/32=256, C/32=2, B=4), block (32,8)
// ---------------------------------------------------------------------------
__global__ void prep_fused_kernel(const float* __restrict__ xyz,
                                  const float* __restrict__ feat) {
    __shared__ float tile[32][33];
    const int tx = threadIdx.x;
    const int ty = threadIdx.y;

    if (blockIdx.y == 0 && blockIdx.z == 0) {
        int i = blockIdx.x * 256 + ty * 32 + tx;
        if (i < BB * NN) {
            float x = xyz[3 * i + 0];
            float y = xyz[3 * i + 1];
            float z = xyz[3 * i + 2];
            g_xyz4[i] = make_float4(x, y, z, 0.0f);
        }
    }

    const int b  = blockIdx.z;
    const int c0 = blockIdx.y * 32;
    const int n0 = blockIdx.x * 32;
    const float* F = feat    + (size_t)b * CC * NN;
    float*       T = g_featT + (size_t)b * NN * CC;

#pragma unroll
    for (int k = 0; k < 32; k += 8)
        tile[ty + k][tx] = F[(size_t)(c0 + ty + k) * NN + (n0 + tx)];
    __syncthreads();
#pragma unroll
    for (int k = 0; k < 32; k += 8)
        T[(size_t)(n0 + ty + k) * CC + (c0 + tx)] = tile[tx][ty + k];
}

// ---------------------------------------------------------------------------
// Kernel A: ellipsoid query only. One warp per query, software-pipelined:
// loads for chunk i+1 are issued before chunk i's ballots so each iteration
// exposes ~max(load_latency, process) instead of their sum.
// Writes fully-padded idx to g_idx.
// ---------------------------------------------------------------------------
__global__ __launch_bounds__(32 * WARPS_PER_BLK, 8)
void query_kernel(const float* __restrict__ new_xyz) {
    __shared__ int s_idx[WARPS_PER_BLK][SS];

    const int w    = threadIdx.x >> 5;
    const int lane = threadIdx.x & 31;
    const int q    = blockIdx.x * WARPS_PER_BLK + w;   // 0 .. B*P-1
    const int b    = q >> 11;                          // P = 2048

    const float nx = new_xyz[(size_t)q * 3 + 0];
    const float ny = new_xyz[(size_t)q * 3 + 1];
    const float nz = new_xyz[(size_t)q * 3 + 2];

    const float4* __restrict__ X = g_xyz4 + b * NN;

    // Prefetch chunk 0 (128 points, 4 x LDG.128 per lane, MLP=4)
    float4 n0 = X[lane];
    float4 n1 = X[lane + 32];
    float4 n2 = X[lane + 64];
    float4 n3 = X[lane + 96];

    int count = 0;
    const unsigned lt_mask = (1u << lane) - 1u;

    for (int base = 0; base < NN; base += 128) {
        float4 p0 = n0, p1 = n1, p2 = n2, p3 = n3;
        const int nb = base + 128;
        if (nb < NN) {                       // issue next chunk's loads NOW
            n0 = X[nb + lane];
            n1 = X[nb + lane + 32];
            n2 = X[nb + lane + 64];
            n3 = X[nb + lane + 96];
        }
        // Process current chunk. Bit-exact vs reference: separately-rounded
        // mul/mul/add; inv_sq rounds to exactly {25.0f, 6.25f, 25.0f}.
        float4 pts[4] = {p0, p1, p2, p3};
#pragma unroll
        for (int j = 0; j < 4; j++) {
            float dx = __fsub_rn(nx, pts[j].x);
            float dy = __fsub_rn(ny, pts[j].y);
            float dz = __fsub_rn(nz, pts[j].z);
            float qx = __fmul_rn(__fmul_rn(dx, dx), 25.0f);
            float qy = __fmul_rn(__fmul_rn(dy, dy), 6.25f);
            float qz = __fmul_rn(__fmul_rn(dz, dz), 25.0f);
            float qv = __fadd_rn(__fadd_rn(qx, qy), qz);
            bool hit = (qv < 1.0f);
            unsigned m = __ballot_sync(0xffffffffu, hit);
            if (hit) {
                int pos = count + __popc(m & lt_mask);
                if (pos < SS) s_idx[w][pos] = base + 32 * j + lane;
            }
            count += __popc(m);
        }
        if (count >= SS) break;              // warp-uniform
    }
    __syncwarp();

    const int cnt   = (count < SS) ? count : SS;
    const int first = (cnt > 0) ? s_idx[w][0] : 0;
    const int id    = (lane < cnt) ? s_idx[w][lane] : first;
    g_idx[(size_t)q * SS + lane] = id;       // coalesced 128B store
}

// ---------------------------------------------------------------------------
// Kernel B: grouping only (uniform work). One warp per query.
// Two-pass smem staging (<=36 channels/pass), STG.128 streaming epilogue.
// ---------------------------------------------------------------------------
__global__ __launch_bounds__(32 * WARPS_PER_BLK, 8)
void group_kernel(const float* __restrict__ new_xyz,
                  float* __restrict__ out) {
    __shared__ float s_st[WARPS_PER_BLK][SS][TPAD];

    const int w    = threadIdx.x >> 5;
    const int lane = threadIdx.x & 31;
    const int q    = blockIdx.x * WARPS_PER_BLK + w;
    const int b    = q >> 11;
    const int p    = q & (PP - 1);

    const int id = g_idx[(size_t)q * SS + lane];   // lane == sample s

    const float nx = new_xyz[(size_t)q * 3 + 0];
    const float ny = new_xyz[(size_t)q * 3 + 1];
    const float nz = new_xyz[(size_t)q * 3 + 2];

    const float4* __restrict__ X  = g_xyz4 + b * NN;
    const float* __restrict__ FT  = g_featT + (size_t)b * NN * CC;
    const size_t chan_stride = (size_t)PP * SS;
    float* ob = out + (size_t)b * NCH * chan_stride + (size_t)p * SS;
    const int cq = lane >> 3;        // channel offset 0..3
    const int sq = lane & 7;         // sample quad 0..7

    // ---- PASS 1: channels 0..35 (xyz, density, feat[0..31])
    float4 pt = X[id];
    float dx = pt.x - nx, dy = pt.y - ny, dz = pt.z - nz;
    float d2 = dx * dx + dy * dy + dz * dz;
    s_st[w][lane][0] = pt.x;
    s_st[w][lane][1] = pt.y;
    s_st[w][lane][2] = pt.z;
    s_st[w][lane][3] = 0.25f * expf(50.0f * d2);   // 1/density

#pragma unroll 8
    for (int s = 0; s < SS; s++) {
        int is = __shfl_sync(0xffffffffu, id, s);
        s_st[w][s][4 + lane] = FT[(size_t)is * CC + lane];   // 128B coalesced
    }
    __syncwarp();

#pragma unroll
    for (int c0 = 0; c0 < 36; c0 += 4) {
        float4 v;
        v.x = s_st[w][4 * sq + 0][c0 + cq];
        v.y = s_st[w][4 * sq + 1][c0 + cq];
        v.z = s_st[w][4 * sq + 2][c0 + cq];
        v.w = s_st[w][4 * sq + 3][c0 + cq];
        __stcs((float4*)(ob + (size_t)(c0 + cq) * chan_stride + 4 * sq), v);
    }
    __syncwarp();

    // ---- PASS 2: channels 36..67 (feat[32..63])
#pragma unroll 8
    for (int s = 0; s < SS; s++) {
        int is = __shfl_sync(0xffffffffu, id, s);
        s_st[w][s][lane] = FT[(size_t)is * CC + 32 + lane];
    }
    __syncwarp();

#pragma unroll
    for (int c0 = 0; c0 < 32; c0 += 4) {
        float4 v;
        v.x = s_st[w][4 * sq + 0][c0 + cq];
        v.y = s_st[w][4 * sq + 1][c0 + cq];
        v.z = s_st[w][4 * sq + 2][c0 + cq];
        v.w = s_st[w][4 * sq + 3][c0 + cq];
        __stcs((float4*)(ob + (size_t)(36 + c0 + cq) * chan_stride + 4 * sq), v);
    }
}

// ---------------------------------------------------------------------------
extern "C" void kernel_launch(void* const* d_in, const int* in_sizes, int n_in,
                              void* d_out, int out_size) {
    const float* xyz     = (const float*)d_in[0];   // (4, 8192, 3)
    const float* new_xyz = (const float*)d_in[1];   // (4, 2048, 3)
    const float* feat    = (const float*)d_in[2];   // (4, 64, 8192)
    float* out           = (float*)d_out;           // (4, 68, 2048, 32)

    dim3 tb(32, 8);
    dim3 tg(NN / 32, CC / 32, BB);
    prep_fused_kernel<<<tg, tb>>>(xyz, feat);

    const int nblk = (BB * PP) / WARPS_PER_BLK;
    query_kernel<<<nblk, 32 * WARPS_PER_BLK>>>(new_xyz);
    group_kernel<<<nblk, 32 * WARPS_PER_BLK>>>(new_xyz, out);
}

// round 11
// speedup vs baseline: 1.1504x; 1.1504x over previous
#include <cuda_runtime.h>
#include <cuda_bf16.h>

// Problem constants
#define BB 4
#define NN 8192
#define PP 2048
#define CC 64
#define SS 32
#define NCH 68          // 3 xyz + 1 density + 64 features
#define WARPS_PER_BLK 4
#define TPAD 37         // 36-channel half-tile + 1 pad (odd -> conflict-free)

// Scratch (device globals: allocation is forbidden)
__device__ float4 g_xyz4[BB * NN];                       // 512 KB, padded xyz
__device__ float  g_featT[(size_t)BB * NN * CC];         // 8 MB, features (B, N, C)

// ---------------------------------------------------------------------------
// Fused prep: (a) xyz (B,N,3) -> float4   (b) transpose features (B,C,N)->(B,N,C)
// grid: (N/32=256, C/32=2, B=4), block (32,8)
// ---------------------------------------------------------------------------
__global__ void prep_fused_kernel(const float* __restrict__ xyz,
                                  const float* __restrict__ feat) {
    __shared__ float tile[32][33];
    const int tx = threadIdx.x;
    const int ty = threadIdx.y;

    if (blockIdx.y == 0 && blockIdx.z == 0) {
        int i = blockIdx.x * 256 + ty * 32 + tx;
        if (i < BB * NN) {
            float x = xyz[3 * i + 0];
            float y = xyz[3 * i + 1];
            float z = xyz[3 * i + 2];
            g_xyz4[i] = make_float4(x, y, z, 0.0f);
        }
    }

    const int b  = blockIdx.z;
    const int c0 = blockIdx.y * 32;
    const int n0 = blockIdx.x * 32;
    const float* F = feat    + (size_t)b * CC * NN;
    float*       T = g_featT + (size_t)b * NN * CC;

#pragma unroll
    for (int k = 0; k < 32; k += 8)
        tile[ty + k][tx] = F[(size_t)(c0 + ty + k) * NN + (n0 + tx)];
    __syncthreads();
#pragma unroll
    for (int k = 0; k < 32; k += 8)
        T[(size_t)(n0 + ty + k) * CC + (c0 + tx)] = tile[tx][ty + k];
}

// ---------------------------------------------------------------------------
// Main (fused): one warp per query point.
//   Phase 1: ellipsoid query, 128 points/iter, DOUBLE-BUFFERED prefetch:
//            chunk i+1's 4 LDG.128 issue before chunk i's ballots, so each
//            iteration exposes ~max(load_latency, process) not their sum.
//   Phase 2: two-pass smem staging (<=36 ch/pass, 19.5 KB/block),
//            STG.128 streaming epilogue.
// ---------------------------------------------------------------------------
__global__ __launch_bounds__(32 * WARPS_PER_BLK, 8)
void query_group_kernel(const float* __restrict__ new_xyz,
                        float* __restrict__ out) {
    __shared__ int   s_idx[WARPS_PER_BLK][SS];
    __shared__ float s_st[WARPS_PER_BLK][SS][TPAD];

    const int w    = threadIdx.x >> 5;
    const int lane = threadIdx.x & 31;
    const int q    = blockIdx.x * WARPS_PER_BLK + w;   // 0 .. B*P-1
    const int b    = q >> 11;                          // P = 2048
    const int p    = q & (PP - 1);

    const float nx = new_xyz[(size_t)q * 3 + 0];
    const float ny = new_xyz[(size_t)q * 3 + 1];
    const float nz = new_xyz[(size_t)q * 3 + 2];

    const float4* __restrict__ X = g_xyz4 + b * NN;

    // ---- Phase 1 (pipelined). Bit-exact vs reference: separately-rounded
    // mul/mul/add; inv_sq rounds to exactly {25.0f, 6.25f, 25.0f}.
    float4 n0 = X[lane];
    float4 n1 = X[lane + 32];
    float4 n2 = X[lane + 64];
    float4 n3 = X[lane + 96];

    int count = 0;
    const unsigned lt_mask = (1u << lane) - 1u;

    for (int base = 0; base < NN; base += 128) {
        float4 pts[4] = {n0, n1, n2, n3};
        const int nb = base + 128;
        if (nb < NN) {                        // issue next chunk's loads NOW
            n0 = X[nb + lane];
            n1 = X[nb + lane + 32];
            n2 = X[nb + lane + 64];
            n3 = X[nb + lane + 96];
        }
#pragma unroll
        for (int j = 0; j < 4; j++) {
            float dx = __fsub_rn(nx, pts[j].x);
            float dy = __fsub_rn(ny, pts[j].y);
            float dz = __fsub_rn(nz, pts[j].z);
            float qx = __fmul_rn(__fmul_rn(dx, dx), 25.0f);
            float qy = __fmul_rn(__fmul_rn(dy, dy), 6.25f);
            float qz = __fmul_rn(__fmul_rn(dz, dz), 25.0f);
            float qv = __fadd_rn(__fadd_rn(qx, qy), qz);
            bool hit = (qv < 1.0f);
            unsigned m = __ballot_sync(0xffffffffu, hit);
            if (hit) {
                int pos = count + __popc(m & lt_mask);
                if (pos < SS) s_idx[w][pos] = base + 32 * j + lane;
            }
            count += __popc(m);
        }
        if (count >= SS) break;               // warp-uniform
    }
    __syncwarp();

    const int cnt   = (count < SS) ? count : SS;
    const int first = (cnt > 0) ? s_idx[w][0] : 0;
    const int id    = (lane < cnt) ? s_idx[w][lane] : first;
    __syncwarp();

    const float* __restrict__ FT = g_featT + (size_t)b * NN * CC;
    const size_t chan_stride = (size_t)PP * SS;
    float* ob = out + (size_t)b * NCH * chan_stride + (size_t)p * SS;
    const int cq = lane >> 3;        // channel offset 0..3
    const int sq = lane & 7;         // sample quad 0..7

    // ================= PASS 1: channels 0..35 (xyz, density, feat[0..31]) ====
    float4 pt = X[id];
    float dx = pt.x - nx, dy = pt.y - ny, dz = pt.z - nz;
    float d2 = dx * dx + dy * dy + dz * dz;
    s_st[w][lane][0] = pt.x;
    s_st[w][lane][1] = pt.y;
    s_st[w][lane][2] = pt.z;
    s_st[w][lane][3] = 0.25f * expf(50.0f * d2);   // 1/density

#pragma unroll 8
    for (int s = 0; s < SS; s++) {
        int is = __shfl_sync(0xffffffffu, id, s);
        s_st[w][s][4 + lane] = FT[(size_t)is * CC + lane];   // 128B coalesced
    }
    __syncwarp();

#pragma unroll
    for (int c0 = 0; c0 < 36; c0 += 4) {
        float4 v;
        v.x = s_st[w][4 * sq + 0][c0 + cq];
        v.y = s_st[w][4 * sq + 1][c0 + cq];
        v.z = s_st[w][4 * sq + 2][c0 + cq];
        v.w = s_st[w][4 * sq + 3][c0 + cq];
        __stcs((float4*)(ob + (size_t)(c0 + cq) * chan_stride + 4 * sq), v);
    }
    __syncwarp();

    // ================= PASS 2: channels 36..67 (feat[32..63]) ================
#pragma unroll 8
    for (int s = 0; s < SS; s++) {
        int is = __shfl_sync(0xffffffffu, id, s);
        s_st[w][s][lane] = FT[(size_t)is * CC + 32 + lane];
    }
    __syncwarp();

#pragma unroll
    for (int c0 = 0; c0 < 32; c0 += 4) {
        float4 v;
        v.x = s_st[w][4 * sq + 0][c0 + cq];
        v.y = s_st[w][4 * sq + 1][c0 + cq];
        v.z = s_st[w][4 * sq + 2][c0 + cq];
        v.w = s_st[w][4 * sq + 3][c0 + cq];
        __stcs((float4*)(ob + (size_t)(36 + c0 + cq) * chan_stride + 4 * sq), v);
    }
}

// ---------------------------------------------------------------------------
extern "C" void kernel_launch(void* const* d_in, const int* in_sizes, int n_in,
                              void* d_out, int out_size) {
    const float* xyz     = (const float*)d_in[0];   // (4, 8192, 3)
    const float* new_xyz = (const float*)d_in[1];   // (4, 2048, 3)
    const float* feat    = (const float*)d_in[2];   // (4, 64, 8192)
    float* out           = (float*)d_out;           // (4, 68, 2048, 32)

    dim3 tb(32, 8);
    dim3 tg(NN / 32, CC / 32, BB);
    prep_fused_kernel<<<tg, tb>>>(xyz, feat);

    query_group_kernel<<<(BB * PP) / WARPS_PER_BLK, 32 * WARPS_PER_BLK>>>(new_xyz, out);
}

// round 13
// speedup vs baseline: 1.2304x; 1.0696x over previous
#include <cuda_runtime.h>
#include <cuda_bf16.h>

// Problem constants
#define BB 4
#define NN 8192
#define PP 2048
#define CC 64
#define SS 32
#define NCH 68          // 3 xyz + 1 density + 64 features
#define WARPS_PER_BLK 4
#define TPAD 37         // 36-channel half-tile + 1 pad (odd -> conflict-free)
#define NQ (BB * PP)
#define NSM 148
#define BLKS_PER_SM 8

// Scratch (device globals: allocation is forbidden)
__device__ float4 g_xyz4[BB * NN];                       // 512 KB, padded xyz
__device__ float  g_featT[(size_t)BB * NN * CC];         // 8 MB, features (B, N, C)
__device__ int    g_ctr;                                 // work-stealing cursor

// ---------------------------------------------------------------------------
// Fused prep: (a) xyz (B,N,3) -> float4  (b) transpose features (B,C,N)->(B,N,C)
//             (c) reset work-stealing counter (same-graph ordering => every
//                 replay starts from 0; deterministic output coverage)
// grid: (N/32=256, C/32=2, B=4), block (32,8)
// ---------------------------------------------------------------------------
__global__ void prep_fused_kernel(const float* __restrict__ xyz,
                                  const float* __restrict__ feat) {
    __shared__ float tile[32][33];
    const int tx = threadIdx.x;
    const int ty = threadIdx.y;

    if (blockIdx.x == 0 && blockIdx.y == 0 && blockIdx.z == 0 && tx == 0 && ty == 0)
        g_ctr = 0;

    if (blockIdx.y == 0 && blockIdx.z == 0) {
        int i = blockIdx.x * 256 + ty * 32 + tx;
        if (i < BB * NN) {
            float x = xyz[3 * i + 0];
            float y = xyz[3 * i + 1];
            float z = xyz[3 * i + 2];
            g_xyz4[i] = make_float4(x, y, z, 0.0f);
        }
    }

    const int b  = blockIdx.z;
    const int c0 = blockIdx.y * 32;
    const int n0 = blockIdx.x * 32;
    const float* F = feat    + (size_t)b * CC * NN;
    float*       T = g_featT + (size_t)b * NN * CC;

#pragma unroll
    for (int k = 0; k < 32; k += 8)
        tile[ty + k][tx] = F[(size_t)(c0 + ty + k) * NN + (n0 + tx)];
    __syncthreads();
#pragma unroll
    for (int k = 0; k < 32; k += 8)
        T[(size_t)(n0 + ty + k) * CC + (c0 + tx)] = tile[tx][ty + k];
}

// ---------------------------------------------------------------------------
// Main: persistent blocks, warp-level work stealing. Per query:
//   Phase 1: ellipsoid scan, 128 pts/iter; 4 independent ballots then a short
//            count/append chain.
//   Phase 2: two-pass smem staging (float4 gather), STG.128 streaming epilogue.
// ---------------------------------------------------------------------------
__global__ __launch_bounds__(32 * WARPS_PER_BLK, BLKS_PER_SM)
void query_group_kernel(const float* __restrict__ new_xyz,
                        float* __restrict__ out) {
    __shared__ int   s_idx[WARPS_PER_BLK][SS];
    __shared__ float s_st[WARPS_PER_BLK][SS][TPAD];

    const int w    = threadIdx.x >> 5;
    const int lane = threadIdx.x & 31;
    const unsigned lt_mask = (1u << lane) - 1u;
    const int cq = lane >> 3;        // epilogue: channel offset 0..3
    const int sq = lane & 7;         // epilogue: sample quad 0..7
    const int sgrp = lane >> 3;      // gather: sample-in-group 0..3
    const int c4   = lane & 7;       // gather: float4 index 0..7
    const size_t chan_stride = (size_t)PP * SS;

    for (;;) {
        // ---- pop next query (warp-uniform)
        int q = 0;
        if (lane == 0) q = atomicAdd(&g_ctr, 1);
        q = __shfl_sync(0xffffffffu, q, 0);
        if (q >= NQ) break;

        const int b = q >> 11;                 // P = 2048
        const int p = q & (PP - 1);

        const float nx = new_xyz[(size_t)q * 3 + 0];
        const float ny = new_xyz[(size_t)q * 3 + 1];
        const float nz = new_xyz[(size_t)q * 3 + 2];

        const float4* __restrict__ X = g_xyz4 + b * NN;

        // ---- Phase 1. Bit-exact vs reference: separately-rounded mul/mul/add;
        // inv_sq rounds to exactly {25.0f, 6.25f, 25.0f}.
        int count = 0;
        for (int base = 0; base < NN; base += 128) {
            float4 pts[4];
            pts[0] = X[base       + lane];
            pts[1] = X[base + 32  + lane];
            pts[2] = X[base + 64  + lane];
            pts[3] = X[base + 96  + lane];

            bool hit[4];
#pragma unroll
            for (int j = 0; j < 4; j++) {
                float dx = __fsub_rn(nx, pts[j].x);
                float dy = __fsub_rn(ny, pts[j].y);
                float dz = __fsub_rn(nz, pts[j].z);
                float qx = __fmul_rn(__fmul_rn(dx, dx), 25.0f);
                float qy = __fmul_rn(__fmul_rn(dy, dy), 6.25f);
                float qz = __fmul_rn(__fmul_rn(dz, dz), 25.0f);
                hit[j] = (__fadd_rn(__fadd_rn(qx, qy), qz) < 1.0f);
            }
            unsigned m[4];
#pragma unroll
            for (int j = 0; j < 4; j++)        // independent votes, pipelined
                m[j] = __ballot_sync(0xffffffffu, hit[j]);
#pragma unroll
            for (int j = 0; j < 4; j++) {      // short serial append chain
                if (hit[j]) {
                    int pos = count + __popc(m[j] & lt_mask);
                    if (pos < SS) s_idx[w][pos] = base + 32 * j + lane;
                }
                count += __popc(m[j]);
            }
            if (count >= SS) break;            // warp-uniform
        }
        __syncwarp();

        const int cnt   = (count < SS) ? count : SS;
        const int first = (cnt > 0) ? s_idx[w][0] : 0;
        const int id    = (lane < cnt) ? s_idx[w][lane] : first;
        __syncwarp();

        const float4* __restrict__ FT4 =
            (const float4*)(g_featT + (size_t)b * NN * CC);
        float* ob = out + (size_t)b * NCH * chan_stride + (size_t)p * SS;

        // ======== PASS 1: channels 0..35 (xyz, density, feat[0..31]) ========
        float4 pt = X[id];
        float dx = pt.x - nx, dy = pt.y - ny, dz = pt.z - nz;
        float d2 = dx * dx + dy * dy + dz * dz;
        s_st[w][lane][0] = pt.x;
        s_st[w][lane][1] = pt.y;
        s_st[w][lane][2] = pt.z;
        s_st[w][lane][3] = 0.25f * expf(50.0f * d2);   // 1/density

        // float4 gather: 4 samples x 8 float4 per iteration (one LDG.128/lane)
#pragma unroll
        for (int s0 = 0; s0 < SS; s0 += 4) {
            int is = __shfl_sync(0xffffffffu, id, s0 + sgrp);
            float4 v = FT4[(size_t)is * 16 + c4];
            float* dst = &s_st[w][s0 + sgrp][4 + 4 * c4];
            dst[0] = v.x; dst[1] = v.y; dst[2] = v.z; dst[3] = v.w;
        }
        __syncwarp();

#pragma unroll
        for (int c0 = 0; c0 < 36; c0 += 4) {
            float4 v;
            v.x = s_st[w][4 * sq + 0][c0 + cq];
            v.y = s_st[w][4 * sq + 1][c0 + cq];
            v.z = s_st[w][4 * sq + 2][c0 + cq];
            v.w = s_st[w][4 * sq + 3][c0 + cq];
            __stcs((float4*)(ob + (size_t)(c0 + cq) * chan_stride + 4 * sq), v);
        }
        __syncwarp();

        // ======== PASS 2: channels 36..67 (feat[32..63]) ====================
#pragma unroll
        for (int s0 = 0; s0 < SS; s0 += 4) {
            int is = __shfl_sync(0xffffffffu, id, s0 + sgrp);
            float4 v = FT4[(size_t)is * 16 + 8 + c4];
            float* dst = &s_st[w][s0 + sgrp][4 * c4];
            dst[0] = v.x; dst[1] = v.y; dst[2] = v.z; dst[3] = v.w;
        }
        __syncwarp();

#pragma unroll
        for (int c0 = 0; c0 < 32; c0 += 4) {
            float4 v;
            v.x = s_st[w][4 * sq + 0][c0 + cq];
            v.y = s_st[w][4 * sq + 1][c0 + cq];
            v.z = s_st[w][4 * sq + 2][c0 + cq];
            v.w = s_st[w][4 * sq + 3][c0 + cq];
            __stcs((float4*)(ob + (size_t)(36 + c0 + cq) * chan_stride + 4 * sq), v);
        }
        __syncwarp();   // smem tile reusable for next popped query
    }
}

// ---------------------------------------------------------------------------
extern "C" void kernel_launch(void* const* d_in, const int* in_sizes, int n_in,
                              void* d_out, int out_size) {
    const float* xyz     = (const float*)d_in[0];   // (4, 8192, 3)
    const float* new_xyz = (const float*)d_in[1];   // (4, 2048, 3)
    const float* feat    = (const float*)d_in[2];   // (4, 64, 8192)
    float* out           = (float*)d_out;           // (4, 68, 2048, 32)

    dim3 tb(32, 8);
    dim3 tg(NN / 32, CC / 32, BB);
    prep_fused_kernel<<<tg, tb>>>(xyz, feat);

    query_group_kernel<<<NSM * BLKS_PER_SM, 32 * WARPS_PER_BLK>>>(new_xyz, out);
}